// round 2
// baseline (speedup 1.0000x reference)
#include <cuda_runtime.h>
#include <cuda_bf16.h>
#include <cstdint>

// ---------------- Problem constants / scratch ----------------
#define MAXN 131072
#define MAXE 2000000
#define GRAPHS 128
#define DIM 64

struct __align__(8) EdgeT { int src; float w; };

__device__ int    g_is64;
__device__ int    g_indeg[MAXN];
__device__ float  g_dinv[MAXN];
__device__ int    g_rowptr[MAXN + 1];
__device__ int    g_cursor[MAXN];
__device__ int    g_blockSums[512];
__device__ EdgeT  g_edges[MAXE];
__device__ float  g_xw[MAXN * DIM];
__device__ float  g_bufA[MAXN * DIM];
__device__ float  g_bufB[MAXN * DIM];
__device__ float  g_gsum[GRAPHS * DIM];
__device__ float  g_gcnt[GRAPHS];

// ---------------- index dtype handling ----------------
__device__ __forceinline__ int loadIdx(const void* p, long long i) {
    if (g_is64) return (int)((const long long*)p)[i];
    return ((const int*)p)[i];
}

// Detect whether index buffers are int64 or int32.
// If int32, reading pairs as int64 yields values with nonzero high words
// (second node id * 2^32) almost everywhere; scan 2048 slots.
__global__ void detect_kernel(const void* eidx, int E, int n_nodes) {
    __shared__ int bad;
    if (threadIdx.x == 0) bad = 0;
    __syncthreads();
    const long long* p = (const long long*)eidx;
    int m = (E < 2048) ? E : 2048;  // safe: int32 buffer holds E int64 slots
    for (int i = threadIdx.x; i < m; i += blockDim.x) {
        long long v = p[i];
        if (v < 0 || v >= (long long)n_nodes) bad = 1;
    }
    __syncthreads();
    if (threadIdx.x == 0) g_is64 = bad ? 0 : 1;
}

// ---------------- setup kernels ----------------
__global__ void zero_kernel(int n) {
    int i = blockIdx.x * blockDim.x + threadIdx.x;
    if (i < n) g_indeg[i] = 0;
    if (i < GRAPHS * DIM) g_gsum[i] = 0.f;
    if (i < GRAPHS) g_gcnt[i] = 0.f;
}

__global__ void deg_kernel(const void* eidx, int E) {
    int e = blockIdx.x * blockDim.x + threadIdx.x;
    if (e >= E) return;
    int d = loadIdx(eidx, (long long)E + e);
    atomicAdd(&g_indeg[d], 1);
}

__global__ void dinv_kernel(int n) {
    int i = blockIdx.x * blockDim.x + threadIdx.x;
    if (i >= n) return;
    g_dinv[i] = rsqrtf((float)(g_indeg[i] + 1));  // +1 self-loop
}

// scan step 1: per-block (1024 elems) exclusive scan of indeg -> rowptr, block total
__global__ void scan1_kernel(int n) {
    __shared__ int sh[256];
    int base = blockIdx.x * 1024 + threadIdx.x * 4;
    int v[4];
#pragma unroll
    for (int i = 0; i < 4; i++) {
        int idx = base + i;
        v[i] = (idx < n) ? g_indeg[idx] : 0;
    }
    int tsum = v[0] + v[1] + v[2] + v[3];
    sh[threadIdx.x] = tsum;
    __syncthreads();
    int val = tsum;
    for (int off = 1; off < 256; off <<= 1) {
        int t = (threadIdx.x >= off) ? sh[threadIdx.x - off] : 0;
        __syncthreads();
        val += t;
        sh[threadIdx.x] = val;
        __syncthreads();
    }
    int run = val - tsum;  // exclusive prefix
#pragma unroll
    for (int i = 0; i < 4; i++) {
        int idx = base + i;
        if (idx < n) g_rowptr[idx] = run;
        run += v[i];
    }
    if (threadIdx.x == 255) g_blockSums[blockIdx.x] = val;
}

// scan step 2: exclusive scan of block sums (nb <= 512)
__global__ void scan2_kernel(int nb) {
    __shared__ int sh[512];
    int t = threadIdx.x;  // 512 threads
    int v = (t < nb) ? g_blockSums[t] : 0;
    sh[t] = v;
    __syncthreads();
    int val = v;
    for (int off = 1; off < 512; off <<= 1) {
        int x = (t >= off) ? sh[t - off] : 0;
        __syncthreads();
        val += x;
        sh[t] = val;
        __syncthreads();
    }
    if (t < nb) g_blockSums[t] = val - v;  // exclusive
}

// scan step 3: add block offsets, init cursor, set rowptr[n]=E
__global__ void scan3_kernel(int n, int E) {
    int idx = blockIdx.x * blockDim.x + threadIdx.x;
    if (idx < n) {
        int val = g_rowptr[idx] + g_blockSums[idx >> 10];
        g_rowptr[idx] = val;
        g_cursor[idx] = val;
    }
    if (idx == 0) g_rowptr[n] = E;
}

__global__ void scatter_kernel(const void* eidx, int E) {
    int e = blockIdx.x * blockDim.x + threadIdx.x;
    if (e >= E) return;
    int s = loadIdx(eidx, e);
    int d = loadIdx(eidx, (long long)E + e);
    float w = g_dinv[s] * g_dinv[d];
    int pos = atomicAdd(&g_cursor[d], 1);
    EdgeT t;
    t.src = s;
    t.w = w;
    g_edges[pos] = t;
}

// ---------------- dense 64x64 GEMM: Y[n,64] = X[n,64] @ W[64,64] ----------------
__global__ void gemm64_kernel(const float* __restrict__ X, const float* __restrict__ W,
                              float* __restrict__ Y, int n) {
    __shared__ float Wsh[64 * 64];
    __shared__ float Xsh[64 * 68];  // padded rows
    int tid = threadIdx.x;  // 256
    int nb = blockIdx.x * 64;
#pragma unroll
    for (int i = tid; i < 1024; i += 256)
        ((float4*)Wsh)[i] = ((const float4*)W)[i];
    for (int i = tid; i < 1024; i += 256) {
        int node = i >> 4;
        int seg = i & 15;
        float4 v = make_float4(0.f, 0.f, 0.f, 0.f);
        if (nb + node < n) v = *(const float4*)(X + (size_t)(nb + node) * 64 + seg * 4);
        *(float4*)(Xsh + node * 68 + seg * 4) = v;
    }
    __syncthreads();
    int tx = tid & 15;       // output col group (4 cols)
    int ty = tid >> 4;       // node group (4 nodes)
    float4 acc[4];
#pragma unroll
    for (int i = 0; i < 4; i++) acc[i] = make_float4(0.f, 0.f, 0.f, 0.f);
    const float* xbase = Xsh + (ty * 4) * 68;
#pragma unroll
    for (int k = 0; k < 64; k += 4) {
        float xr[4][4];
#pragma unroll
        for (int i = 0; i < 4; i++)
            *(float4*)xr[i] = *(const float4*)(xbase + i * 68 + k);
#pragma unroll
        for (int j = 0; j < 4; j++) {
            float4 w4 = *(const float4*)(Wsh + (k + j) * 64 + tx * 4);
#pragma unroll
            for (int i = 0; i < 4; i++) {
                float xs = xr[i][j];
                acc[i].x += xs * w4.x;
                acc[i].y += xs * w4.y;
                acc[i].z += xs * w4.z;
                acc[i].w += xs * w4.w;
            }
        }
    }
#pragma unroll
    for (int i = 0; i < 4; i++) {
        int node = nb + ty * 4 + i;
        if (node < n) *(float4*)(Y + (size_t)node * 64 + tx * 4) = acc[i];
    }
}

// ---------------- edge aggregation: one warp per dst node ----------------
__global__ void aggregate_kernel(const float* __restrict__ xw, float* __restrict__ out,
                                 const float* __restrict__ bias, int relu, int n) {
    int warp = (blockIdx.x * blockDim.x + threadIdx.x) >> 5;
    int lane = threadIdx.x & 31;
    if (warp >= n) return;
    int start = g_rowptr[warp];
    int end = g_rowptr[warp + 1];
    float dv = g_dinv[warp];
    float wself = dv * dv;
    float2 sv = *(const float2*)(xw + (size_t)warp * 64 + lane * 2);
    float accx = wself * sv.x;
    float accy = wself * sv.y;
    int e = start;
    for (; e + 4 <= end; e += 4) {
        EdgeT e0 = g_edges[e];
        EdgeT e1 = g_edges[e + 1];
        EdgeT e2 = g_edges[e + 2];
        EdgeT e3 = g_edges[e + 3];
        float2 v0 = *(const float2*)(xw + (size_t)e0.src * 64 + lane * 2);
        float2 v1 = *(const float2*)(xw + (size_t)e1.src * 64 + lane * 2);
        float2 v2 = *(const float2*)(xw + (size_t)e2.src * 64 + lane * 2);
        float2 v3 = *(const float2*)(xw + (size_t)e3.src * 64 + lane * 2);
        accx += e0.w * v0.x; accy += e0.w * v0.y;
        accx += e1.w * v1.x; accy += e1.w * v1.y;
        accx += e2.w * v2.x; accy += e2.w * v2.y;
        accx += e3.w * v3.x; accy += e3.w * v3.y;
    }
    for (; e < end; e++) {
        EdgeT et = g_edges[e];
        float2 v = *(const float2*)(xw + (size_t)et.src * 64 + lane * 2);
        accx += et.w * v.x;
        accy += et.w * v.y;
    }
    float2 b2 = *(const float2*)(bias + lane * 2);
    float ox = accx + b2.x;
    float oy = accy + b2.y;
    if (relu) {
        ox = fmaxf(ox, 0.f);
        oy = fmaxf(oy, 0.f);
    }
    float2 o;
    o.x = ox;
    o.y = oy;
    *(float2*)(out + (size_t)warp * 64 + lane * 2) = o;
}

// ---------------- global mean pool ----------------
__global__ void pool_kernel(const float* __restrict__ h, const void* batch, int n) {
    int node = (blockIdx.x * blockDim.x + threadIdx.x) >> 5;
    int lane = threadIdx.x & 31;
    if (node >= n) return;
    int g = loadIdx(batch, node);
    float2 v = *(const float2*)(h + (size_t)node * 64 + lane * 2);
    atomicAdd(&g_gsum[g * 64 + lane * 2], v.x);
    atomicAdd(&g_gsum[g * 64 + lane * 2 + 1], v.y);
    if (lane == 0) atomicAdd(&g_gcnt[g], 1.0f);
}

// ---------------- final linear: out[g,c] = mean[g] @ Wlin + blin ----------------
__global__ void final_kernel(const float* __restrict__ Wlin, const float* __restrict__ blin,
                             float* __restrict__ out) {
    int g = blockIdx.x;
    int c = threadIdx.x;
    __shared__ float mean[64];
    float cnt = fmaxf(g_gcnt[g], 1.0f);
    mean[c] = g_gsum[g * 64 + c] / cnt;
    __syncthreads();
    float acc = blin[c];
#pragma unroll
    for (int k = 0; k < 64; k++) acc += mean[k] * Wlin[k * 64 + c];
    out[g * 64 + c] = acc;
}

// ---------------- launch ----------------
extern "C" void kernel_launch(void* const* d_in, const int* in_sizes, int n_in,
                              void* d_out, int out_size) {
    const float* x    = (const float*)d_in[0];
    const void*  eidx = d_in[1];
    const void*  batch = d_in[2];
    const float* W1 = (const float*)d_in[3];
    const float* b1 = (const float*)d_in[4];
    const float* W2 = (const float*)d_in[5];
    const float* b2 = (const float*)d_in[6];
    const float* W3 = (const float*)d_in[7];
    const float* b3 = (const float*)d_in[8];
    const float* Wlin = (const float*)d_in[9];
    const float* blin = (const float*)d_in[10];
    float* out = (float*)d_out;

    int N = in_sizes[0] / DIM;
    int E = in_sizes[1] / 2;

    float *xw, *bufA, *bufB;
    cudaGetSymbolAddress((void**)&xw, g_xw);
    cudaGetSymbolAddress((void**)&bufA, g_bufA);
    cudaGetSymbolAddress((void**)&bufB, g_bufB);

    detect_kernel<<<1, 256>>>(eidx, E, N);

    int zn = N > GRAPHS * DIM ? N : GRAPHS * DIM;
    zero_kernel<<<(zn + 255) / 256, 256>>>(N);
    deg_kernel<<<(E + 255) / 256, 256>>>(eidx, E);
    dinv_kernel<<<(N + 255) / 256, 256>>>(N);

    int nb1 = (N + 1023) / 1024;
    scan1_kernel<<<nb1, 256>>>(N);
    scan2_kernel<<<1, 512>>>(nb1);
    scan3_kernel<<<(N + 255) / 256, 256>>>(N, E);
    scatter_kernel<<<(E + 255) / 256, 256>>>(eidx, E);

    int gemmBlocks = (N + 63) / 64;
    int aggBlocks = (N * 32 + 255) / 256;

    // layer 1
    gemm64_kernel<<<gemmBlocks, 256>>>(x, W1, xw, N);
    aggregate_kernel<<<aggBlocks, 256>>>(xw, bufA, b1, 1, N);
    // layer 2
    gemm64_kernel<<<gemmBlocks, 256>>>(bufA, W2, xw, N);
    aggregate_kernel<<<aggBlocks, 256>>>(xw, bufB, b2, 1, N);
    // layer 3
    gemm64_kernel<<<gemmBlocks, 256>>>(bufB, W3, xw, N);
    aggregate_kernel<<<aggBlocks, 256>>>(xw, bufA, b3, 0, N);

    pool_kernel<<<aggBlocks, 256>>>(bufA, batch, N);
    final_kernel<<<GRAPHS, DIM>>>(Wlin, blin, out);
}

// round 3
// speedup vs baseline: 1.3499x; 1.3499x over previous
#include <cuda_runtime.h>
#include <cuda_fp16.h>
#include <cstdint>

// ---------------- Problem constants / scratch ----------------
#define MAXN 131072
#define MAXE 2000000
#define GRAPHS 128
#define DIM 64

struct __align__(8) EdgeT { int src; float w; };

__device__ int     g_is64;
__device__ int     g_indeg[MAXN];
__device__ float   g_dinv[MAXN];
__device__ int     g_rowptr[MAXN + 1];
__device__ int     g_cursor[MAXN];
__device__ int     g_blockSums[512];
__device__ EdgeT   g_edges[MAXE];
__device__ __half2 g_xw[MAXN * 32];      // fp16 transformed features (gather payload)
__device__ float   g_bufA[MAXN * DIM];
__device__ float   g_bufB[MAXN * DIM];

// ---------------- index dtype handling ----------------
__device__ __forceinline__ int loadIdx(const void* p, long long i) {
    if (g_is64) return (int)((const long long*)p)[i];
    return ((const int*)p)[i];
}

// ---------------- setup: zero indeg + detect int32/int64 ----------------
__global__ void zero_detect_kernel(const void* eidx, int E, int n) {
    int i = blockIdx.x * blockDim.x + threadIdx.x;
    if (i < n) g_indeg[i] = 0;
    if (blockIdx.x == 0) {
        __shared__ int bad;
        if (threadIdx.x == 0) bad = 0;
        __syncthreads();
        const long long* p = (const long long*)eidx;
        int m = (E < 2048) ? E : 2048;  // int32 buffer holds >= E int64 slots
        for (int j = threadIdx.x; j < m; j += blockDim.x) {
            long long v = p[j];
            if (v < 0 || v >= (long long)n) bad = 1;
        }
        __syncthreads();
        if (threadIdx.x == 0) g_is64 = bad ? 0 : 1;
    }
}

__global__ void deg_kernel(const void* eidx, int E) {
    int e = blockIdx.x * blockDim.x + threadIdx.x;
    if (e >= E) return;
    int d = loadIdx(eidx, (long long)E + e);
    atomicAdd(&g_indeg[d], 1);
}

// scan step 1: per-block (1024 elems) exclusive scan of indeg -> rowptr; also dinv
__global__ void scan1_kernel(int n) {
    __shared__ int sh[256];
    int base = blockIdx.x * 1024 + threadIdx.x * 4;
    int v[4];
#pragma unroll
    for (int i = 0; i < 4; i++) {
        int idx = base + i;
        v[i] = (idx < n) ? g_indeg[idx] : 0;
        if (idx < n) g_dinv[idx] = rsqrtf((float)(v[i] + 1));  // +1 self-loop
    }
    int tsum = v[0] + v[1] + v[2] + v[3];
    sh[threadIdx.x] = tsum;
    __syncthreads();
    int val = tsum;
    for (int off = 1; off < 256; off <<= 1) {
        int t = (threadIdx.x >= off) ? sh[threadIdx.x - off] : 0;
        __syncthreads();
        val += t;
        sh[threadIdx.x] = val;
        __syncthreads();
    }
    int run = val - tsum;  // exclusive prefix
#pragma unroll
    for (int i = 0; i < 4; i++) {
        int idx = base + i;
        if (idx < n) g_rowptr[idx] = run;
        run += v[i];
    }
    if (threadIdx.x == 255) g_blockSums[blockIdx.x] = val;
}

// scan step 2: exclusive scan of block sums (nb <= 512)
__global__ void scan2_kernel(int nb) {
    __shared__ int sh[512];
    int t = threadIdx.x;
    int v = (t < nb) ? g_blockSums[t] : 0;
    sh[t] = v;
    __syncthreads();
    int val = v;
    for (int off = 1; off < 512; off <<= 1) {
        int x = (t >= off) ? sh[t - off] : 0;
        __syncthreads();
        val += x;
        sh[t] = val;
        __syncthreads();
    }
    if (t < nb) g_blockSums[t] = val - v;
}

// scan step 3: add block offsets, init cursor, set rowptr[n]=E
__global__ void scan3_kernel(int n, int E) {
    int idx = blockIdx.x * blockDim.x + threadIdx.x;
    if (idx < n) {
        int val = g_rowptr[idx] + g_blockSums[idx >> 10];
        g_rowptr[idx] = val;
        g_cursor[idx] = val;
    }
    if (idx == 0) g_rowptr[n] = E;
}

__global__ void scatter_kernel(const void* eidx, int E) {
    int e = blockIdx.x * blockDim.x + threadIdx.x;
    if (e >= E) return;
    int s = loadIdx(eidx, e);
    int d = loadIdx(eidx, (long long)E + e);
    float w = g_dinv[s] * g_dinv[d];
    int pos = atomicAdd(&g_cursor[d], 1);
    EdgeT t;
    t.src = s;
    t.w = w;
    g_edges[pos] = t;
}

// ---------------- dense 64x64 GEMM: Y[n,64](fp16) = X[n,64](fp32) @ W ----------------
__global__ void gemm64_kernel(const float* __restrict__ X, const float* __restrict__ W,
                              __half* __restrict__ Y, int n) {
    __shared__ float Wsh[64 * 64];
    __shared__ float Xsh[64 * 68];  // padded rows
    int tid = threadIdx.x;  // 256
    int nb = blockIdx.x * 64;
#pragma unroll
    for (int i = tid; i < 1024; i += 256)
        ((float4*)Wsh)[i] = ((const float4*)W)[i];
    for (int i = tid; i < 1024; i += 256) {
        int node = i >> 4;
        int seg = i & 15;
        float4 v = make_float4(0.f, 0.f, 0.f, 0.f);
        if (nb + node < n) v = *(const float4*)(X + (size_t)(nb + node) * 64 + seg * 4);
        *(float4*)(Xsh + node * 68 + seg * 4) = v;
    }
    __syncthreads();
    int tx = tid & 15;       // output col group (4 cols)
    int ty = tid >> 4;       // node group (4 nodes)
    float4 acc[4];
#pragma unroll
    for (int i = 0; i < 4; i++) acc[i] = make_float4(0.f, 0.f, 0.f, 0.f);
    const float* xbase = Xsh + (ty * 4) * 68;
#pragma unroll
    for (int k = 0; k < 64; k += 4) {
        float xr[4][4];
#pragma unroll
        for (int i = 0; i < 4; i++)
            *(float4*)xr[i] = *(const float4*)(xbase + i * 68 + k);
#pragma unroll
        for (int j = 0; j < 4; j++) {
            float4 w4 = *(const float4*)(Wsh + (k + j) * 64 + tx * 4);
#pragma unroll
            for (int i = 0; i < 4; i++) {
                float xs = xr[i][j];
                acc[i].x += xs * w4.x;
                acc[i].y += xs * w4.y;
                acc[i].z += xs * w4.z;
                acc[i].w += xs * w4.w;
            }
        }
    }
#pragma unroll
    for (int i = 0; i < 4; i++) {
        int node = nb + ty * 4 + i;
        if (node < n) {
            __half2 p0 = __floats2half2_rn(acc[i].x, acc[i].y);
            __half2 p1 = __floats2half2_rn(acc[i].z, acc[i].w);
            uint2 u;
            u.x = *(unsigned*)&p0;
            u.y = *(unsigned*)&p1;
            ((uint2*)Y)[(size_t)node * 16 + tx] = u;
        }
    }
}

// ---------------- edge aggregation: one warp per dst node, fp16 gather ----------------
__global__ void aggregate_kernel(const __half2* __restrict__ xw, float* __restrict__ out,
                                 const float* __restrict__ bias, int relu, int n) {
    int warp = (blockIdx.x * blockDim.x + threadIdx.x) >> 5;
    int lane = threadIdx.x & 31;
    if (warp >= n) return;
    int start = g_rowptr[warp];
    int end = g_rowptr[warp + 1];
    float dv = g_dinv[warp];
    float wself = dv * dv;
    float2 sv = __half22float2(xw[(size_t)warp * 32 + lane]);
    float accx = wself * sv.x;
    float accy = wself * sv.y;
    int e = start;
    for (; e + 4 <= end; e += 4) {
        EdgeT e0 = g_edges[e];
        EdgeT e1 = g_edges[e + 1];
        EdgeT e2 = g_edges[e + 2];
        EdgeT e3 = g_edges[e + 3];
        float2 v0 = __half22float2(xw[(size_t)e0.src * 32 + lane]);
        float2 v1 = __half22float2(xw[(size_t)e1.src * 32 + lane]);
        float2 v2 = __half22float2(xw[(size_t)e2.src * 32 + lane]);
        float2 v3 = __half22float2(xw[(size_t)e3.src * 32 + lane]);
        accx += e0.w * v0.x; accy += e0.w * v0.y;
        accx += e1.w * v1.x; accy += e1.w * v1.y;
        accx += e2.w * v2.x; accy += e2.w * v2.y;
        accx += e3.w * v3.x; accy += e3.w * v3.y;
    }
    for (; e < end; e++) {
        EdgeT et = g_edges[e];
        float2 v = __half22float2(xw[(size_t)et.src * 32 + lane]);
        accx += et.w * v.x;
        accy += et.w * v.y;
    }
    float2 b2 = *(const float2*)(bias + lane * 2);
    float ox = accx + b2.x;
    float oy = accy + b2.y;
    if (relu) {
        ox = fmaxf(ox, 0.f);
        oy = fmaxf(oy, 0.f);
    }
    float2 o;
    o.x = ox;
    o.y = oy;
    *(float2*)(out + (size_t)warp * 64 + lane * 2) = o;
}

// ---------------- fused pool + linear: batch is sorted -> contiguous ranges ----------------
__device__ __forceinline__ int lower_bound_batch(const void* batch, int n, int key) {
    int lo = 0, hi = n;
    while (lo < hi) {
        int mid = (lo + hi) >> 1;
        if (loadIdx(batch, mid) < key) lo = mid + 1;
        else hi = mid;
    }
    return lo;
}

__global__ void poolfinal_kernel(const float* __restrict__ h, const void* batch,
                                 const float* __restrict__ Wlin, const float* __restrict__ blin,
                                 float* __restrict__ out, int n) {
    int g = blockIdx.x;
    int tid = threadIdx.x;  // 256
    __shared__ int s_lo, s_hi;
    if (tid == 0) s_lo = lower_bound_batch(batch, n, g);
    if (tid == 1) s_hi = lower_bound_batch(batch, n, g + 1);
    __syncthreads();
    int lo = s_lo, hi = s_hi;
    int dim = tid & 63;
    int sub = tid >> 6;  // 0..3
    float acc = 0.f;
    for (int node = lo + sub; node < hi; node += 4)
        acc += h[(size_t)node * 64 + dim];
    __shared__ float red[256];
    __shared__ float mean[64];
    red[tid] = acc;
    __syncthreads();
    if (tid < 64) {
        float s = red[tid] + red[tid + 64] + red[tid + 128] + red[tid + 192];
        float cnt = (float)(hi - lo);
        mean[tid] = s / fmaxf(cnt, 1.0f);
    }
    __syncthreads();
    if (tid < 64) {
        float a = blin[tid];
#pragma unroll
        for (int k = 0; k < 64; k++) a += mean[k] * Wlin[k * 64 + tid];
        out[g * 64 + tid] = a;
    }
}

// ---------------- launch ----------------
extern "C" void kernel_launch(void* const* d_in, const int* in_sizes, int n_in,
                              void* d_out, int out_size) {
    const float* x     = (const float*)d_in[0];
    const void*  eidx  = d_in[1];
    const void*  batch = d_in[2];
    const float* W1 = (const float*)d_in[3];
    const float* b1 = (const float*)d_in[4];
    const float* W2 = (const float*)d_in[5];
    const float* b2 = (const float*)d_in[6];
    const float* W3 = (const float*)d_in[7];
    const float* b3 = (const float*)d_in[8];
    const float* Wlin = (const float*)d_in[9];
    const float* blin = (const float*)d_in[10];
    float* out = (float*)d_out;

    int N = in_sizes[0] / DIM;
    int E = in_sizes[1] / 2;

    __half2 *xw2;
    float *bufA, *bufB;
    cudaGetSymbolAddress((void**)&xw2, g_xw);
    cudaGetSymbolAddress((void**)&bufA, g_bufA);
    cudaGetSymbolAddress((void**)&bufB, g_bufB);
    __half* xw = (__half*)xw2;

    zero_detect_kernel<<<(N + 255) / 256, 256>>>(eidx, E, N);
    deg_kernel<<<(E + 255) / 256, 256>>>(eidx, E);

    int nb1 = (N + 1023) / 1024;
    scan1_kernel<<<nb1, 256>>>(N);
    scan2_kernel<<<1, 512>>>(nb1);
    scan3_kernel<<<(N + 255) / 256, 256>>>(N, E);
    scatter_kernel<<<(E + 255) / 256, 256>>>(eidx, E);

    int gemmBlocks = (N + 63) / 64;
    int aggBlocks = (N * 32 + 255) / 256;

    // layer 1
    gemm64_kernel<<<gemmBlocks, 256>>>(x, W1, xw, N);
    aggregate_kernel<<<aggBlocks, 256>>>(xw2, bufA, b1, 1, N);
    // layer 2
    gemm64_kernel<<<gemmBlocks, 256>>>(bufA, W2, xw, N);
    aggregate_kernel<<<aggBlocks, 256>>>(xw2, bufB, b2, 1, N);
    // layer 3
    gemm64_kernel<<<gemmBlocks, 256>>>(bufB, W3, xw, N);
    aggregate_kernel<<<aggBlocks, 256>>>(xw2, bufA, b3, 0, N);

    poolfinal_kernel<<<GRAPHS, 256>>>(bufA, batch, Wlin, blin, out, N);
}

// round 4
// speedup vs baseline: 1.6271x; 1.2054x over previous
#include <cuda_runtime.h>
#include <cuda_fp16.h>
#include <cuda_fp8.h>
#include <cstdint>

// ---------------- Problem constants / scratch ----------------
#define MAXN 131072
#define MAXE 2000000
#define GRAPHS 128
#define DIM 64

struct __align__(8) EdgeT { int src; float w; };

__device__ int     g_is64;
__device__ int     g_indeg[MAXN];
__device__ float   g_dinv[MAXN];
__device__ int     g_rowptr[MAXN + 1];
__device__ int     g_cursor[MAXN];
__device__ int     g_blockSums[512];
__device__ EdgeT   g_edges[MAXE];
__device__ uint4   g_xw[MAXN * 4];       // fp8 e4m3 payload, 64 B per node
__device__ __half  g_bufA[MAXN * DIM];
__device__ __half  g_bufB[MAXN * DIM];

// ---------------- index dtype handling ----------------
__device__ __forceinline__ int loadIdx(const void* p, long long i) {
    if (g_is64) return (int)((const long long*)p)[i];
    return ((const int*)p)[i];
}

// ---------------- detect int32 vs int64 indices ----------------
__global__ void detect_kernel(const void* eidx, int E, int n) {
    __shared__ int bad;
    if (threadIdx.x == 0) bad = 0;
    __syncthreads();
    const long long* p = (const long long*)eidx;
    int m = (E < 2048) ? E : 2048;
    for (int j = threadIdx.x; j < m; j += blockDim.x) {
        long long v = p[j];
        if (v < 0 || v >= (long long)n) bad = 1;
    }
    __syncthreads();
    if (threadIdx.x == 0) g_is64 = bad ? 0 : 1;
}

__global__ void deg_kernel(const void* eidx, int E) {
    int e = blockIdx.x * blockDim.x + threadIdx.x;
    if (e >= E) return;
    int d = loadIdx(eidx, (long long)E + e);
    atomicAdd(&g_indeg[d], 1);
}

// scan step 1: per-block (1024) exclusive scan of indeg -> rowptr; dinv; re-zero indeg
__global__ void scan1_kernel(int n) {
    __shared__ int sh[256];
    int base = blockIdx.x * 1024 + threadIdx.x * 4;
    int v[4];
#pragma unroll
    for (int i = 0; i < 4; i++) {
        int idx = base + i;
        v[i] = (idx < n) ? g_indeg[idx] : 0;
        if (idx < n) {
            g_dinv[idx] = rsqrtf((float)(v[i] + 1));  // +1 self-loop
            g_indeg[idx] = 0;                          // re-arm for next launch
        }
    }
    int tsum = v[0] + v[1] + v[2] + v[3];
    sh[threadIdx.x] = tsum;
    __syncthreads();
    int val = tsum;
    for (int off = 1; off < 256; off <<= 1) {
        int t = (threadIdx.x >= off) ? sh[threadIdx.x - off] : 0;
        __syncthreads();
        val += t;
        sh[threadIdx.x] = val;
        __syncthreads();
    }
    int run = val - tsum;
#pragma unroll
    for (int i = 0; i < 4; i++) {
        int idx = base + i;
        if (idx < n) g_rowptr[idx] = run;
        run += v[i];
    }
    if (threadIdx.x == 255) g_blockSums[blockIdx.x] = val;
}

// scan step 2+3 fused: each block reduces its needed prefix of blockSums (<=128 entries)
__global__ void scan3_kernel(int n, int E) {
    __shared__ int red[256];
    int t = threadIdx.x;
    int chunk = blockIdx.x >> 2;   // which 1024-chunk this block belongs to
    red[t] = (t < chunk) ? g_blockSums[t] : 0;
    __syncthreads();
    for (int off = 128; off > 0; off >>= 1) {
        if (t < off) red[t] += red[t + off];
        __syncthreads();
    }
    int offset = red[0];
    int idx = blockIdx.x * 256 + t;
    if (idx < n) {
        int val = g_rowptr[idx] + offset;
        g_rowptr[idx] = val;
        g_cursor[idx] = val;
    }
    if (idx == 0) g_rowptr[n] = E;
}

__global__ void scatter_kernel(const void* eidx, int E) {
    int e = blockIdx.x * blockDim.x + threadIdx.x;
    if (e >= E) return;
    int s = loadIdx(eidx, e);
    int d = loadIdx(eidx, (long long)E + e);
    float w = g_dinv[s] * g_dinv[d];
    int pos = atomicAdd(&g_cursor[d], 1);
    EdgeT t;
    t.src = s;
    t.w = w;
    g_edges[pos] = t;
}

// ---------------- tensor-core GEMM: Y[n,64](fp8) = X[n,64] @ W[64,64] ----------------
// 256 threads = 8 warps, each warp does a 16x64 output tile via mma.m16n8k16.
template <bool IN_HALF>
__global__ void gemm_mma_kernel(const void* __restrict__ Xv, const float* __restrict__ W,
                                uint4* __restrict__ Y, int n) {
    __shared__ __half Wh[64 * 72];
    __shared__ __half Xsh[128 * 72];
    __shared__ uint8_t Ysh[128 * 64];
    int tid = threadIdx.x;
    int warp = tid >> 5, lane = tid & 31;
    int nb = blockIdx.x * 128;

    // load W fp32 -> fp16 smem (row=k stride 72)
    for (int i = tid; i < 1024; i += 256) {
        float4 v = ((const float4*)W)[i];
        int row = i >> 4, c4 = (i & 15) * 4;
        __half2 p0 = __floats2half2_rn(v.x, v.y);
        __half2 p1 = __floats2half2_rn(v.z, v.w);
        uint2 u;
        u.x = *(unsigned*)&p0;
        u.y = *(unsigned*)&p1;
        *(uint2*)&Wh[row * 72 + c4] = u;
    }
    // load X rows -> fp16 smem
    for (int i = tid; i < 2048; i += 256) {
        int row = i >> 4, seg = i & 15;  // seg: 4-elem group
        uint2 u;
        if (nb + row < n) {
            if (IN_HALF) {
                u = ((const uint2*)Xv)[(size_t)(nb + row) * 16 + seg];
            } else {
                float4 v = ((const float4*)Xv)[(size_t)(nb + row) * 16 + seg];
                __half2 p0 = __floats2half2_rn(v.x, v.y);
                __half2 p1 = __floats2half2_rn(v.z, v.w);
                u.x = *(unsigned*)&p0;
                u.y = *(unsigned*)&p1;
            }
        } else {
            u.x = 0; u.y = 0;
        }
        *(uint2*)&Xsh[row * 72 + seg * 4] = u;
    }
    __syncthreads();

    int r0 = warp * 16;
    // A fragments for all 4 k-chunks via ldmatrix.x4
    uint32_t A[4][4];
#pragma unroll
    for (int kc = 0; kc < 4; kc++) {
        const __half* ap = &Xsh[(r0 + (lane & 15)) * 72 + kc * 16 + (lane >> 4) * 8];
        uint32_t sa = (uint32_t)__cvta_generic_to_shared(ap);
        asm volatile("ldmatrix.sync.aligned.m8n8.x4.shared.b16 {%0,%1,%2,%3}, [%4];"
                     : "=r"(A[kc][0]), "=r"(A[kc][1]), "=r"(A[kc][2]), "=r"(A[kc][3])
                     : "r"(sa));
    }
    float D[8][4];
#pragma unroll
    for (int nc = 0; nc < 8; nc++)
#pragma unroll
        for (int j = 0; j < 4; j++) D[nc][j] = 0.f;

    int kq = 2 * (lane & 3);
    int cq = lane >> 2;
#pragma unroll
    for (int kc = 0; kc < 4; kc++) {
#pragma unroll
        for (int nc = 0; nc < 8; nc++) {
            int kr = kc * 16 + kq;
            int col = nc * 8 + cq;
            __half2 b0 = __halves2half2(Wh[kr * 72 + col], Wh[(kr + 1) * 72 + col]);
            __half2 b1 = __halves2half2(Wh[(kr + 8) * 72 + col], Wh[(kr + 9) * 72 + col]);
            uint32_t B0 = *(uint32_t*)&b0;
            uint32_t B1 = *(uint32_t*)&b1;
            asm volatile(
                "mma.sync.aligned.m16n8k16.row.col.f32.f16.f16.f32 "
                "{%0,%1,%2,%3}, {%4,%5,%6,%7}, {%8,%9}, {%0,%1,%2,%3};"
                : "+f"(D[nc][0]), "+f"(D[nc][1]), "+f"(D[nc][2]), "+f"(D[nc][3])
                : "r"(A[kc][0]), "r"(A[kc][1]), "r"(A[kc][2]), "r"(A[kc][3]),
                  "r"(B0), "r"(B1));
        }
    }
    // epilogue: fp32 -> fp8 e4m3 into smem staging (warp-local rows)
    int g = lane >> 2;
    int cb = 2 * (lane & 3);
#pragma unroll
    for (int nc = 0; nc < 8; nc++) {
        float2 lo = make_float2(D[nc][0], D[nc][1]);
        float2 hi = make_float2(D[nc][2], D[nc][3]);
        unsigned short p0 = __nv_cvt_float2_to_fp8x2(lo, __NV_SATFINITE, __NV_E4M3);
        unsigned short p1 = __nv_cvt_float2_to_fp8x2(hi, __NV_SATFINITE, __NV_E4M3);
        *(unsigned short*)&Ysh[(r0 + g) * 64 + nc * 8 + cb] = p0;
        *(unsigned short*)&Ysh[(r0 + g + 8) * 64 + nc * 8 + cb] = p1;
    }
    __syncwarp();
    // coalesced copy: 16 rows x 64B = 64 uint4 per warp
#pragma unroll
    for (int j = 0; j < 2; j++) {
        int idx = j * 32 + lane;
        int row = idx >> 2, q = idx & 3;
        int node = nb + r0 + row;
        if (node < n)
            Y[(size_t)node * 4 + q] = ((const uint4*)Ysh)[(r0 + row) * 4 + q];
    }
}

// ---------------- edge aggregation: one warp per dst node, fp8 gather ----------------
__device__ __forceinline__ float2 fp8pair(const uint8_t* base, int node, int lane) {
    unsigned short us = ((const unsigned short*)(base + (size_t)node * 64))[lane];
    __half2_raw hr = __nv_cvt_fp8x2_to_halfraw2(us, __NV_E4M3);
    return __half22float2(*(__half2*)&hr);
}

__global__ void aggregate_kernel(const uint8_t* __restrict__ xw, __half* __restrict__ out,
                                 const float* __restrict__ bias, int relu, int n) {
    int warp = (blockIdx.x * blockDim.x + threadIdx.x) >> 5;
    int lane = threadIdx.x & 31;
    if (warp >= n) return;
    int start = g_rowptr[warp];
    int end = g_rowptr[warp + 1];
    float dv = g_dinv[warp];
    float wself = dv * dv;
    float2 sv = fp8pair(xw, warp, lane);
    float accx = wself * sv.x;
    float accy = wself * sv.y;
    int e = start;
    for (; e + 4 <= end; e += 4) {
        EdgeT e0 = g_edges[e];
        EdgeT e1 = g_edges[e + 1];
        EdgeT e2 = g_edges[e + 2];
        EdgeT e3 = g_edges[e + 3];
        float2 v0 = fp8pair(xw, e0.src, lane);
        float2 v1 = fp8pair(xw, e1.src, lane);
        float2 v2 = fp8pair(xw, e2.src, lane);
        float2 v3 = fp8pair(xw, e3.src, lane);
        accx += e0.w * v0.x; accy += e0.w * v0.y;
        accx += e1.w * v1.x; accy += e1.w * v1.y;
        accx += e2.w * v2.x; accy += e2.w * v2.y;
        accx += e3.w * v3.x; accy += e3.w * v3.y;
    }
    for (; e < end; e++) {
        EdgeT et = g_edges[e];
        float2 v = fp8pair(xw, et.src, lane);
        accx += et.w * v.x;
        accy += et.w * v.y;
    }
    float2 b2 = *(const float2*)(bias + lane * 2);
    float ox = accx + b2.x;
    float oy = accy + b2.y;
    if (relu) {
        ox = fmaxf(ox, 0.f);
        oy = fmaxf(oy, 0.f);
    }
    __half2 o = __floats2half2_rn(ox, oy);
    ((__half2*)out)[(size_t)warp * 32 + lane] = o;
}

// ---------------- fused pool + linear (batch sorted -> contiguous ranges) ----------------
__device__ __forceinline__ int lower_bound_batch(const void* batch, int n, int key) {
    int lo = 0, hi = n;
    while (lo < hi) {
        int mid = (lo + hi) >> 1;
        if (loadIdx(batch, mid) < key) lo = mid + 1;
        else hi = mid;
    }
    return lo;
}

__global__ void poolfinal_kernel(const __half* __restrict__ h, const void* batch,
                                 const float* __restrict__ Wlin, const float* __restrict__ blin,
                                 float* __restrict__ out, int n) {
    int g = blockIdx.x;
    int tid = threadIdx.x;  // 256
    __shared__ int s_lo, s_hi;
    if (tid == 0) s_lo = lower_bound_batch(batch, n, g);
    if (tid == 1) s_hi = lower_bound_batch(batch, n, g + 1);
    __syncthreads();
    int lo = s_lo, hi = s_hi;
    int dim = tid & 63;
    int sub = tid >> 6;  // 0..3
    float acc = 0.f;
    for (int node = lo + sub; node < hi; node += 4)
        acc += __half2float(h[(size_t)node * 64 + dim]);
    __shared__ float red[256];
    __shared__ float mean[64];
    red[tid] = acc;
    __syncthreads();
    if (tid < 64) {
        float s = red[tid] + red[tid + 64] + red[tid + 128] + red[tid + 192];
        float cnt = (float)(hi - lo);
        mean[tid] = s / fmaxf(cnt, 1.0f);
    }
    __syncthreads();
    if (tid < 64) {
        float a = blin[tid];
#pragma unroll
        for (int k = 0; k < 64; k++) a += mean[k] * Wlin[k * 64 + tid];
        out[g * 64 + tid] = a;
    }
}

// ---------------- launch ----------------
extern "C" void kernel_launch(void* const* d_in, const int* in_sizes, int n_in,
                              void* d_out, int out_size) {
    const float* x     = (const float*)d_in[0];
    const void*  eidx  = d_in[1];
    const void*  batch = d_in[2];
    const float* W1 = (const float*)d_in[3];
    const float* b1 = (const float*)d_in[4];
    const float* W2 = (const float*)d_in[5];
    const float* b2 = (const float*)d_in[6];
    const float* W3 = (const float*)d_in[7];
    const float* b3 = (const float*)d_in[8];
    const float* Wlin = (const float*)d_in[9];
    const float* blin = (const float*)d_in[10];
    float* out = (float*)d_out;

    int N = in_sizes[0] / DIM;
    int E = in_sizes[1] / 2;

    uint4* xw4;
    __half *bufA, *bufB;
    cudaGetSymbolAddress((void**)&xw4, g_xw);
    cudaGetSymbolAddress((void**)&bufA, g_bufA);
    cudaGetSymbolAddress((void**)&bufB, g_bufB);
    const uint8_t* xw8 = (const uint8_t*)xw4;

    detect_kernel<<<1, 256>>>(eidx, E, N);
    deg_kernel<<<(E + 255) / 256, 256>>>(eidx, E);

    int nb1 = (N + 1023) / 1024;
    scan1_kernel<<<nb1, 256>>>(N);
    scan3_kernel<<<(N + 255) / 256, 256>>>(N, E);
    scatter_kernel<<<(E + 255) / 256, 256>>>(eidx, E);

    int gemmBlocks = (N + 127) / 128;
    int aggBlocks = (N * 32 + 255) / 256;

    // layer 1
    gemm_mma_kernel<false><<<gemmBlocks, 256>>>(x, W1, xw4, N);
    aggregate_kernel<<<aggBlocks, 256>>>(xw8, bufA, b1, 1, N);
    // layer 2
    gemm_mma_kernel<true><<<gemmBlocks, 256>>>(bufA, W2, xw4, N);
    aggregate_kernel<<<aggBlocks, 256>>>(xw8, bufB, b2, 1, N);
    // layer 3
    gemm_mma_kernel<true><<<gemmBlocks, 256>>>(bufB, W3, xw4, N);
    aggregate_kernel<<<aggBlocks, 256>>>(xw8, bufA, b3, 0, N);

    poolfinal_kernel<<<GRAPHS, 256>>>(bufA, batch, Wlin, blin, out, N);
}

// round 5
// speedup vs baseline: 1.7785x; 1.0930x over previous
#include <cuda_runtime.h>
#include <cuda_fp16.h>
#include <cuda_fp8.h>
#include <cstdint>

// ---------------- Problem constants / scratch ----------------
#define MAXN 131072
#define MAXE 2000000
#define GRAPHS 128
#define DIM 64

struct __align__(8) EdgeT { int src; float w; };

__device__ int     g_is64;
__device__ int     g_indeg[MAXN];
__device__ float   g_dinv[MAXN];
__device__ int     g_rowptr[MAXN + 1];
__device__ int     g_cursor[MAXN];
__device__ int     g_blockSums[512];
__device__ EdgeT   g_edges[MAXE];
__device__ uint4   g_xw[MAXN * 4];       // fp8 e4m3 payload, 64 B per node
__device__ __half  g_bufA[MAXN * DIM];
__device__ __half  g_bufB[MAXN * DIM];

// ---------------- index dtype handling ----------------
__device__ __forceinline__ int loadIdx(const void* p, long long i) {
    if (g_is64) return (int)((const long long*)p)[i];
    return ((const int*)p)[i];
}

// ---------------- detect int32 vs int64 indices ----------------
__global__ void detect_kernel(const void* eidx, int E, int n) {
    __shared__ int bad;
    if (threadIdx.x == 0) bad = 0;
    __syncthreads();
    const long long* p = (const long long*)eidx;
    int m = (E < 2048) ? E : 2048;
    for (int j = threadIdx.x; j < m; j += blockDim.x) {
        long long v = p[j];
        if (v < 0 || v >= (long long)n) bad = 1;
    }
    __syncthreads();
    if (threadIdx.x == 0) g_is64 = bad ? 0 : 1;
}

__global__ void deg_kernel(const void* eidx, int E) {
    int e = blockIdx.x * blockDim.x + threadIdx.x;
    if (e >= E) return;
    int d = loadIdx(eidx, (long long)E + e);
    atomicAdd(&g_indeg[d], 1);
}

// scan step 1: per-block (1024) exclusive scan of indeg -> rowptr; dinv; re-zero indeg
__global__ void scan1_kernel(int n) {
    __shared__ int sh[256];
    int base = blockIdx.x * 1024 + threadIdx.x * 4;
    int v[4];
#pragma unroll
    for (int i = 0; i < 4; i++) {
        int idx = base + i;
        v[i] = (idx < n) ? g_indeg[idx] : 0;
        if (idx < n) {
            g_dinv[idx] = rsqrtf((float)(v[i] + 1));  // +1 self-loop
            g_indeg[idx] = 0;                          // re-arm for next launch
        }
    }
    int tsum = v[0] + v[1] + v[2] + v[3];
    sh[threadIdx.x] = tsum;
    __syncthreads();
    int val = tsum;
    for (int off = 1; off < 256; off <<= 1) {
        int t = (threadIdx.x >= off) ? sh[threadIdx.x - off] : 0;
        __syncthreads();
        val += t;
        sh[threadIdx.x] = val;
        __syncthreads();
    }
    int run = val - tsum;
#pragma unroll
    for (int i = 0; i < 4; i++) {
        int idx = base + i;
        if (idx < n) g_rowptr[idx] = run;
        run += v[i];
    }
    if (threadIdx.x == 255) g_blockSums[blockIdx.x] = val;
}

// scan step 2+3 fused: each block reduces its needed prefix of blockSums
__global__ void scan3_kernel(int n, int E) {
    __shared__ int red[256];
    int t = threadIdx.x;
    int chunk = blockIdx.x >> 2;   // which 1024-chunk this block belongs to
    red[t] = (t < chunk) ? g_blockSums[t] : 0;
    __syncthreads();
    for (int off = 128; off > 0; off >>= 1) {
        if (t < off) red[t] += red[t + off];
        __syncthreads();
    }
    int offset = red[0];
    int idx = blockIdx.x * 256 + t;
    if (idx < n) {
        int val = g_rowptr[idx] + offset;
        g_rowptr[idx] = val;
        g_cursor[idx] = val;
    }
    if (idx == 0) g_rowptr[n] = E;
}

__global__ void scatter_kernel(const void* eidx, int E) {
    int e = blockIdx.x * blockDim.x + threadIdx.x;
    if (e >= E) return;
    int s = loadIdx(eidx, e);
    int d = loadIdx(eidx, (long long)E + e);
    float w = g_dinv[s] * g_dinv[d];
    int pos = atomicAdd(&g_cursor[d], 1);
    EdgeT t;
    t.src = s;
    t.w = w;
    g_edges[pos] = t;
}

// ---------------- tensor-core GEMM: Y[n,64](fp8) = X[n,64] @ W[64,64] ----------------
template <bool IN_HALF>
__global__ void gemm_mma_kernel(const void* __restrict__ Xv, const float* __restrict__ W,
                                uint4* __restrict__ Y, int n) {
    __shared__ __half Wh[64 * 72];
    __shared__ __half Xsh[128 * 72];
    __shared__ uint8_t Ysh[128 * 64];
    int tid = threadIdx.x;
    int warp = tid >> 5, lane = tid & 31;
    int nb = blockIdx.x * 128;

    for (int i = tid; i < 1024; i += 256) {
        float4 v = ((const float4*)W)[i];
        int row = i >> 4, c4 = (i & 15) * 4;
        __half2 p0 = __floats2half2_rn(v.x, v.y);
        __half2 p1 = __floats2half2_rn(v.z, v.w);
        uint2 u;
        u.x = *(unsigned*)&p0;
        u.y = *(unsigned*)&p1;
        *(uint2*)&Wh[row * 72 + c4] = u;
    }
    for (int i = tid; i < 2048; i += 256) {
        int row = i >> 4, seg = i & 15;
        uint2 u;
        if (nb + row < n) {
            if (IN_HALF) {
                u = ((const uint2*)Xv)[(size_t)(nb + row) * 16 + seg];
            } else {
                float4 v = ((const float4*)Xv)[(size_t)(nb + row) * 16 + seg];
                __half2 p0 = __floats2half2_rn(v.x, v.y);
                __half2 p1 = __floats2half2_rn(v.z, v.w);
                u.x = *(unsigned*)&p0;
                u.y = *(unsigned*)&p1;
            }
        } else {
            u.x = 0; u.y = 0;
        }
        *(uint2*)&Xsh[row * 72 + seg * 4] = u;
    }
    __syncthreads();

    int r0 = warp * 16;
    uint32_t A[4][4];
#pragma unroll
    for (int kc = 0; kc < 4; kc++) {
        const __half* ap = &Xsh[(r0 + (lane & 15)) * 72 + kc * 16 + (lane >> 4) * 8];
        uint32_t sa = (uint32_t)__cvta_generic_to_shared(ap);
        asm volatile("ldmatrix.sync.aligned.m8n8.x4.shared.b16 {%0,%1,%2,%3}, [%4];"
                     : "=r"(A[kc][0]), "=r"(A[kc][1]), "=r"(A[kc][2]), "=r"(A[kc][3])
                     : "r"(sa));
    }
    float D[8][4];
#pragma unroll
    for (int nc = 0; nc < 8; nc++)
#pragma unroll
        for (int j = 0; j < 4; j++) D[nc][j] = 0.f;

    int kq = 2 * (lane & 3);
    int cq = lane >> 2;
#pragma unroll
    for (int kc = 0; kc < 4; kc++) {
#pragma unroll
        for (int nc = 0; nc < 8; nc++) {
            int kr = kc * 16 + kq;
            int col = nc * 8 + cq;
            __half2 b0 = __halves2half2(Wh[kr * 72 + col], Wh[(kr + 1) * 72 + col]);
            __half2 b1 = __halves2half2(Wh[(kr + 8) * 72 + col], Wh[(kr + 9) * 72 + col]);
            uint32_t B0 = *(uint32_t*)&b0;
            uint32_t B1 = *(uint32_t*)&b1;
            asm volatile(
                "mma.sync.aligned.m16n8k16.row.col.f32.f16.f16.f32 "
                "{%0,%1,%2,%3}, {%4,%5,%6,%7}, {%8,%9}, {%0,%1,%2,%3};"
                : "+f"(D[nc][0]), "+f"(D[nc][1]), "+f"(D[nc][2]), "+f"(D[nc][3])
                : "r"(A[kc][0]), "r"(A[kc][1]), "r"(A[kc][2]), "r"(A[kc][3]),
                  "r"(B0), "r"(B1));
        }
    }
    int g = lane >> 2;
    int cb = 2 * (lane & 3);
#pragma unroll
    for (int nc = 0; nc < 8; nc++) {
        float2 lo = make_float2(D[nc][0], D[nc][1]);
        float2 hi = make_float2(D[nc][2], D[nc][3]);
        unsigned short p0 = __nv_cvt_float2_to_fp8x2(lo, __NV_SATFINITE, __NV_E4M3);
        unsigned short p1 = __nv_cvt_float2_to_fp8x2(hi, __NV_SATFINITE, __NV_E4M3);
        *(unsigned short*)&Ysh[(r0 + g) * 64 + nc * 8 + cb] = p0;
        *(unsigned short*)&Ysh[(r0 + g + 8) * 64 + nc * 8 + cb] = p1;
    }
    __syncwarp();
#pragma unroll
    for (int j = 0; j < 2; j++) {
        int idx = j * 32 + lane;
        int row = idx >> 2, q = idx & 3;
        int node = nb + r0 + row;
        if (node < n)
            Y[(size_t)node * 4 + q] = ((const uint4*)Ysh)[(r0 + row) * 4 + q];
    }
}

// ---------------- edge aggregation: one warp per dst node, fp8 gather, MLP=8 ----------------
__device__ __forceinline__ float2 fp8pair(const uint8_t* base, int node, int lane) {
    unsigned short us = ((const unsigned short*)(base + (size_t)node * 64))[lane];
    __half2_raw hr = __nv_cvt_fp8x2_to_halfraw2(us, __NV_E4M3);
    return __half22float2(*(__half2*)&hr);
}

__global__ void aggregate_kernel(const uint8_t* __restrict__ xw, __half* __restrict__ out,
                                 const float* __restrict__ bias, int relu, int n) {
    int warp = (blockIdx.x * blockDim.x + threadIdx.x) >> 5;
    int lane = threadIdx.x & 31;
    if (warp >= n) return;
    int start = g_rowptr[warp];
    int end = g_rowptr[warp + 1];
    float dv = g_dinv[warp];
    float wself = dv * dv;
    float2 sv = fp8pair(xw, warp, lane);
    float accx = wself * sv.x;
    float accy = wself * sv.y;
    int e = start;
    // 8-deep software pipeline: 8 independent edge loads, then 8 independent gathers
    for (; e + 8 <= end; e += 8) {
        EdgeT ed[8];
#pragma unroll
        for (int i = 0; i < 8; i++) ed[i] = g_edges[e + i];
        float2 v[8];
#pragma unroll
        for (int i = 0; i < 8; i++) v[i] = fp8pair(xw, ed[i].src, lane);
#pragma unroll
        for (int i = 0; i < 8; i++) {
            accx += ed[i].w * v[i].x;
            accy += ed[i].w * v[i].y;
        }
    }
    for (; e + 2 <= end; e += 2) {
        EdgeT e0 = g_edges[e];
        EdgeT e1 = g_edges[e + 1];
        float2 v0 = fp8pair(xw, e0.src, lane);
        float2 v1 = fp8pair(xw, e1.src, lane);
        accx += e0.w * v0.x; accy += e0.w * v0.y;
        accx += e1.w * v1.x; accy += e1.w * v1.y;
    }
    if (e < end) {
        EdgeT et = g_edges[e];
        float2 v = fp8pair(xw, et.src, lane);
        accx += et.w * v.x;
        accy += et.w * v.y;
    }
    float2 b2 = *(const float2*)(bias + lane * 2);
    float ox = accx + b2.x;
    float oy = accy + b2.y;
    if (relu) {
        ox = fmaxf(ox, 0.f);
        oy = fmaxf(oy, 0.f);
    }
    __half2 o = __floats2half2_rn(ox, oy);
    ((__half2*)out)[(size_t)warp * 32 + lane] = o;
}

// ---------------- fused pool + linear (batch sorted -> contiguous ranges) ----------------
__device__ __forceinline__ int lower_bound_batch(const void* batch, int n, int key) {
    int lo = 0, hi = n;
    while (lo < hi) {
        int mid = (lo + hi) >> 1;
        if (loadIdx(batch, mid) < key) lo = mid + 1;
        else hi = mid;
    }
    return lo;
}

__global__ void poolfinal_kernel(const __half* __restrict__ h, const void* batch,
                                 const float* __restrict__ Wlin, const float* __restrict__ blin,
                                 float* __restrict__ out, int n) {
    int g = blockIdx.x;
    int tid = threadIdx.x;  // 256
    __shared__ int s_lo, s_hi;
    if (tid == 0) s_lo = lower_bound_batch(batch, n, g);
    if (tid == 1) s_hi = lower_bound_batch(batch, n, g + 1);
    __syncthreads();
    int lo = s_lo, hi = s_hi;
    int dim = tid & 63;
    int sub = tid >> 6;  // 0..3
    float acc = 0.f;
    for (int node = lo + sub; node < hi; node += 4)
        acc += __half2float(h[(size_t)node * 64 + dim]);
    __shared__ float red[256];
    __shared__ float mean[64];
    red[tid] = acc;
    __syncthreads();
    if (tid < 64) {
        float s = red[tid] + red[tid + 64] + red[tid + 128] + red[tid + 192];
        float cnt = (float)(hi - lo);
        mean[tid] = s / fmaxf(cnt, 1.0f);
    }
    __syncthreads();
    if (tid < 64) {
        float a = blin[tid];
#pragma unroll
        for (int k = 0; k < 64; k++) a += mean[k] * Wlin[k * 64 + tid];
        out[g * 64 + tid] = a;
    }
}

// ---------------- launch ----------------
extern "C" void kernel_launch(void* const* d_in, const int* in_sizes, int n_in,
                              void* d_out, int out_size) {
    const float* x     = (const float*)d_in[0];
    const void*  eidx  = d_in[1];
    const void*  batch = d_in[2];
    const float* W1 = (const float*)d_in[3];
    const float* b1 = (const float*)d_in[4];
    const float* W2 = (const float*)d_in[5];
    const float* b2 = (const float*)d_in[6];
    const float* W3 = (const float*)d_in[7];
    const float* b3 = (const float*)d_in[8];
    const float* Wlin = (const float*)d_in[9];
    const float* blin = (const float*)d_in[10];
    float* out = (float*)d_out;

    int N = in_sizes[0] / DIM;
    int E = in_sizes[1] / 2;

    uint4* xw4;
    __half *bufA, *bufB;
    cudaGetSymbolAddress((void**)&xw4, g_xw);
    cudaGetSymbolAddress((void**)&bufA, g_bufA);
    cudaGetSymbolAddress((void**)&bufB, g_bufB);
    const uint8_t* xw8 = (const uint8_t*)xw4;

    // side stream + events for fork-join overlap (created once, reused; no device mem)
    static cudaStream_t s2 = nullptr;
    static cudaEvent_t evFork = nullptr, evJoin = nullptr;
    if (!s2) {
        cudaStreamCreateWithFlags(&s2, cudaStreamNonBlocking);
        cudaEventCreateWithFlags(&evFork, cudaEventDisableTiming);
        cudaEventCreateWithFlags(&evJoin, cudaEventDisableTiming);
    }

    int gemmBlocks = (N + 127) / 128;
    int aggBlocks = (N * 32 + 255) / 256;
    int nb1 = (N + 1023) / 1024;

    // fork: layer-1 GEMM (depends only on x, W1) runs concurrently with edge setup
    cudaEventRecord(evFork, 0);
    cudaStreamWaitEvent(s2, evFork, 0);
    gemm_mma_kernel<false><<<gemmBlocks, 256, 0, s2>>>(x, W1, xw4, N);
    cudaEventRecord(evJoin, s2);

    // edge setup chain on default stream
    detect_kernel<<<1, 256>>>(eidx, E, N);
    deg_kernel<<<(E + 255) / 256, 256>>>(eidx, E);
    scan1_kernel<<<nb1, 256>>>(N);
    scan3_kernel<<<(N + 255) / 256, 256>>>(N, E);
    scatter_kernel<<<(E + 255) / 256, 256>>>(eidx, E);

    // join: aggregate-1 needs both the CSR and xw from the forked GEMM
    cudaStreamWaitEvent(0, evJoin, 0);

    aggregate_kernel<<<aggBlocks, 256>>>(xw8, bufA, b1, 1, N);
    // layer 2
    gemm_mma_kernel<true><<<gemmBlocks, 256>>>(bufA, W2, xw4, N);
    aggregate_kernel<<<aggBlocks, 256>>>(xw8, bufB, b2, 1, N);
    // layer 3
    gemm_mma_kernel<true><<<gemmBlocks, 256>>>(bufB, W3, xw4, N);
    aggregate_kernel<<<aggBlocks, 256>>>(xw8, bufA, b3, 0, N);

    poolfinal_kernel<<<GRAPHS, 256>>>(bufA, batch, Wlin, blin, out, N);
}